// round 4
// baseline (speedup 1.0000x reference)
#include <cuda_runtime.h>

// Problem constants
#define BB 8
#define NN 1024
#define FF 2048
#define CC 4
#define NTOK (BB * NN)            // 8192 tokens
#define VEC_ELEMS (BB * NN * FF)  // 16777216 floats
#define BCN (BB * CC)             // 32 (b,c) pairs

// Scratch (static device globals — no allocation allowed)
__device__ float g_Wpart[16][8][2048];  // [h-chunk][row r][f], r = c + 4*half
__device__ float g_W[8 * 2048];         // Weff rows: r<4 -> Wa[c], r>=4 -> Wb[c]
__device__ float g_cst[4];              // W2 @ b1 + b2
__device__ float g_EA[BCN * NN];        // exp(p1[b,n,c] + const[c]),  [(b*4+c)*1024 + n]
__device__ float g_EB[BCN * NN];        // exp(p2[b,n,c])

// ---------------------------------------------------------------------------
// Kernel 1: partial Weff[r][f] = sum_{h in chunk} W2[c][h] * W1[h][f']
// grid (16, 16): blockIdx.x -> 256-wide f' group, blockIdx.y -> 64-wide h chunk
// ---------------------------------------------------------------------------
__global__ void k1_weff_part(const float* __restrict__ W1,
                             const float* __restrict__ W2) {
    __shared__ float sW2[4 * 64];
    const int tid = threadIdx.x;
    const int h0 = blockIdx.y * 64;
    if (tid < 256) sW2[tid] = W2[(tid >> 6) * 1024 + h0 + (tid & 63)];
    __syncthreads();

    const int fp = blockIdx.x * 256 + tid;  // 0..4095 (column of W1)
    float a0 = 0.f, a1 = 0.f, a2 = 0.f, a3 = 0.f;
    const float* w1p = W1 + (size_t)h0 * 4096 + fp;
#pragma unroll 16
    for (int hh = 0; hh < 64; hh++) {
        float w1 = w1p[(size_t)hh * 4096];  // coalesced across warp
        a0 = fmaf(sW2[hh], w1, a0);
        a1 = fmaf(sW2[64 + hh], w1, a1);
        a2 = fmaf(sW2[128 + hh], w1, a2);
        a3 = fmaf(sW2[192 + hh], w1, a3);
    }
    const int half = fp >> 11;          // 0: Wa, 1: Wb
    const int f = fp & 2047;
    const int rb = half * 4;
    g_Wpart[blockIdx.y][rb + 0][f] = a0;
    g_Wpart[blockIdx.y][rb + 1][f] = a1;
    g_Wpart[blockIdx.y][rb + 2][f] = a2;
    g_Wpart[blockIdx.y][rb + 3][f] = a3;
}

// ---------------------------------------------------------------------------
// Kernel 1b: reduce partials into g_W; one warp also computes g_cst
// ---------------------------------------------------------------------------
__global__ void k1b_reduce(const float* __restrict__ W2,
                           const float* __restrict__ b1,
                           const float* __restrict__ b2) {
    const int idx = blockIdx.x * 256 + threadIdx.x;  // 0..16383
    const int r = idx >> 11, f = idx & 2047;
    float s = 0.f;
#pragma unroll
    for (int p = 0; p < 16; p++) s += g_Wpart[p][r][f];
    g_W[r * 2048 + f] = s;

    if (blockIdx.x == 0 && threadIdx.x < 32) {
        const int lane = threadIdx.x;
        float c0 = 0.f, c1 = 0.f, c2 = 0.f, c3 = 0.f;
        for (int h = lane; h < 1024; h += 32) {
            float bv = b1[h];
            c0 = fmaf(W2[h], bv, c0);
            c1 = fmaf(W2[1024 + h], bv, c1);
            c2 = fmaf(W2[2048 + h], bv, c2);
            c3 = fmaf(W2[3072 + h], bv, c3);
        }
#pragma unroll
        for (int off = 16; off; off >>= 1) {
            c0 += __shfl_xor_sync(~0u, c0, off);
            c1 += __shfl_xor_sync(~0u, c1, off);
            c2 += __shfl_xor_sync(~0u, c2, off);
            c3 += __shfl_xor_sync(~0u, c3, off);
        }
        if (lane == 0) {
            g_cst[0] = c0 + b2[0];
            g_cst[1] = c1 + b2[1];
            g_cst[2] = c2 + b2[2];
            g_cst[3] = c3 + b2[3];
        }
    }
}

// ---------------------------------------------------------------------------
// Kernel 2: per-token projections + fused vectors copy.
// One warp per 2 TOKENS (16 accs -> ~60 regs -> 3-4 blocks/SM occupancy),
// with software-pipelined v prefetch and streaming hints.
// 8 warps/block -> 16 tokens/block; grid = 512 blocks.
// ---------------------------------------------------------------------------
__global__ void __launch_bounds__(256) k2_proj(const float4* __restrict__ vec4,
                                               float4* __restrict__ outv4) {
    const int lane = threadIdx.x & 31;
    const int wid = threadIdx.x >> 5;
    const int t0 = (blockIdx.x * 8 + wid) * 2;  // base token of this warp

    const float4* gW4 = reinterpret_cast<const float4*>(g_W);
    const float4* vp = vec4 + (size_t)t0 * 512;
    float4* op = outv4 + (size_t)t0 * 512;

    float acc[8][2];
#pragma unroll
    for (int r = 0; r < 8; r++) {
        acc[r][0] = 0.f;
        acc[r][1] = 0.f;
    }

    // Prefetch first k-step's vectors (streaming loads — no reuse).
    float4 v0 = __ldcs(&vp[lane]);
    float4 v1 = __ldcs(&vp[512 + lane]);

#pragma unroll
    for (int k = 0; k < 16; k++) {
        const int i = lane + 32 * k;
        float4 nv0, nv1;
        if (k < 15) {                     // prefetch next k-step
            nv0 = __ldcs(&vp[i + 32]);
            nv1 = __ldcs(&vp[512 + i + 32]);
        }
        __stcs(&op[i], v0);               // fused streaming copy into output
        __stcs(&op[512 + i], v1);
#pragma unroll
        for (int r = 0; r < 8; r++) {
            float4 w = gW4[r * 512 + i];  // L1/L2-resident (64 KB total)
            acc[r][0] = fmaf(v0.x, w.x, acc[r][0]);
            acc[r][0] = fmaf(v0.y, w.y, acc[r][0]);
            acc[r][0] = fmaf(v0.z, w.z, acc[r][0]);
            acc[r][0] = fmaf(v0.w, w.w, acc[r][0]);
            acc[r][1] = fmaf(v1.x, w.x, acc[r][1]);
            acc[r][1] = fmaf(v1.y, w.y, acc[r][1]);
            acc[r][1] = fmaf(v1.z, w.z, acc[r][1]);
            acc[r][1] = fmaf(v1.w, w.w, acc[r][1]);
        }
        v0 = nv0;
        v1 = nv1;
    }

#pragma unroll
    for (int r = 0; r < 8; r++)
#pragma unroll
        for (int t = 0; t < 2; t++)
#pragma unroll
            for (int off = 16; off; off >>= 1)
                acc[r][t] += __shfl_xor_sync(~0u, acc[r][t], off);

    if (lane == 0) {
#pragma unroll
        for (int t = 0; t < 2; t++) {
            const int token = t0 + t;
            const int b = token >> 10, n = token & 1023;
            const int base = b * 4 * 1024 + n;
#pragma unroll
            for (int c = 0; c < 4; c++) {
                g_EA[base + c * 1024] = __expf(acc[c][t] + g_cst[c]);
                g_EB[base + c * 1024] = __expf(acc[4 + c][t]);
            }
        }
    }
}

// ---------------------------------------------------------------------------
// Kernel 3: connections[b,c,m,n] = t/(1+t),  t = EA[b,c,n] * EB[b,c,m]
// grid (64, 32): blockIdx.y = (b*4+c), blockIdx.x = 16-row m tile.
// ---------------------------------------------------------------------------
__global__ void k3_conn(float4* __restrict__ conn4) {
    const int tid = threadIdx.x;       // 0..255 -> float4 group along n
    const int bc = blockIdx.y;         // 0..31
    const int m0 = blockIdx.x * 16;

    const float4* ea4 = reinterpret_cast<const float4*>(g_EA);
    float4 ea = __ldg(&ea4[bc * 256 + tid]);

    size_t obase = ((size_t)bc * 1024 + m0) * 256 + tid;
#pragma unroll
    for (int j = 0; j < 16; j++) {
        float eb = __ldg(&g_EB[bc * 1024 + m0 + j]);  // broadcast load
        float4 o;
        float t;
        t = ea.x * eb; o.x = __fdividef(t, 1.0f + t);
        t = ea.y * eb; o.y = __fdividef(t, 1.0f + t);
        t = ea.z * eb; o.z = __fdividef(t, 1.0f + t);
        t = ea.w * eb; o.w = __fdividef(t, 1.0f + t);
        conn4[obase + (size_t)j * 256] = o;
    }
}

// ---------------------------------------------------------------------------
extern "C" void kernel_launch(void* const* d_in, const int* in_sizes, int n_in,
                              void* d_out, int out_size) {
    const float* vectors = (const float*)d_in[0];
    const float* W1 = (const float*)d_in[1];
    const float* b1 = (const float*)d_in[2];
    const float* W2 = (const float*)d_in[3];
    const float* b2 = (const float*)d_in[4];
    float* out = (float*)d_out;

    k1_weff_part<<<dim3(16, 16), 256>>>(W1, W2);
    k1b_reduce<<<64, 256>>>(W2, b1, b2);
    k2_proj<<<512, 256>>>((const float4*)vectors, (float4*)out);
    k3_conn<<<dim3(64, 32), 256>>>((float4*)(out + VEC_ELEMS));
}

// round 5
// speedup vs baseline: 1.0274x; 1.0274x over previous
#include <cuda_runtime.h>

// Problem constants
#define BB 8
#define NN 1024
#define FF 2048
#define CC 4
#define NTOK (BB * NN)            // 8192 tokens
#define VEC_ELEMS (BB * NN * FF)  // 16777216 floats
#define BCN (BB * CC)             // 32 (b,c) pairs

// Scratch (static device globals — no allocation allowed)
__device__ float g_Wpart[16][8][2048];  // [h-chunk][row r][f], r = c + 4*half
__device__ float g_W[8 * 2048];         // Weff rows: r<4 -> Wa[c], r>=4 -> Wb[c]
__device__ float g_cst[4];              // W2 @ b1 + b2
__device__ float g_EA[BCN * NN];        // exp(p1[b,n,c] + const[c]),  [(b*4+c)*1024 + n]
__device__ float g_EB[BCN * NN];        // exp(p2[b,n,c])

// ---------------------------------------------------------------------------
// Kernel 1: partial Weff[r][f] = sum_{h in chunk} W2[c][h] * W1[h][f']
// grid (16, 16): blockIdx.x -> 256-wide f' group, blockIdx.y -> 64-wide h chunk
// ---------------------------------------------------------------------------
__global__ void k1_weff_part(const float* __restrict__ W1,
                             const float* __restrict__ W2) {
    __shared__ float sW2[4 * 64];
    const int tid = threadIdx.x;
    const int h0 = blockIdx.y * 64;
    if (tid < 256) sW2[tid] = W2[(tid >> 6) * 1024 + h0 + (tid & 63)];
    __syncthreads();

    const int fp = blockIdx.x * 256 + tid;  // 0..4095 (column of W1)
    float a0 = 0.f, a1 = 0.f, a2 = 0.f, a3 = 0.f;
    const float* w1p = W1 + (size_t)h0 * 4096 + fp;
#pragma unroll 16
    for (int hh = 0; hh < 64; hh++) {
        float w1 = w1p[(size_t)hh * 4096];  // coalesced across warp
        a0 = fmaf(sW2[hh], w1, a0);
        a1 = fmaf(sW2[64 + hh], w1, a1);
        a2 = fmaf(sW2[128 + hh], w1, a2);
        a3 = fmaf(sW2[192 + hh], w1, a3);
    }
    const int half = fp >> 11;          // 0: Wa, 1: Wb
    const int f = fp & 2047;
    const int rb = half * 4;
    g_Wpart[blockIdx.y][rb + 0][f] = a0;
    g_Wpart[blockIdx.y][rb + 1][f] = a1;
    g_Wpart[blockIdx.y][rb + 2][f] = a2;
    g_Wpart[blockIdx.y][rb + 3][f] = a3;
}

// ---------------------------------------------------------------------------
// Kernel 1b: reduce partials into g_W; one warp also computes g_cst
// ---------------------------------------------------------------------------
__global__ void k1b_reduce(const float* __restrict__ W2,
                           const float* __restrict__ b1,
                           const float* __restrict__ b2) {
    const int idx = blockIdx.x * 256 + threadIdx.x;  // 0..16383
    const int r = idx >> 11, f = idx & 2047;
    float s = 0.f;
#pragma unroll
    for (int p = 0; p < 16; p++) s += g_Wpart[p][r][f];
    g_W[r * 2048 + f] = s;

    if (blockIdx.x == 0 && threadIdx.x < 32) {
        const int lane = threadIdx.x;
        float c0 = 0.f, c1 = 0.f, c2 = 0.f, c3 = 0.f;
        for (int h = lane; h < 1024; h += 32) {
            float bv = b1[h];
            c0 = fmaf(W2[h], bv, c0);
            c1 = fmaf(W2[1024 + h], bv, c1);
            c2 = fmaf(W2[2048 + h], bv, c2);
            c3 = fmaf(W2[3072 + h], bv, c3);
        }
#pragma unroll
        for (int off = 16; off; off >>= 1) {
            c0 += __shfl_xor_sync(~0u, c0, off);
            c1 += __shfl_xor_sync(~0u, c1, off);
            c2 += __shfl_xor_sync(~0u, c2, off);
            c3 += __shfl_xor_sync(~0u, c3, off);
        }
        if (lane == 0) {
            g_cst[0] = c0 + b2[0];
            g_cst[1] = c1 + b2[1];
            g_cst[2] = c2 + b2[2];
            g_cst[3] = c3 + b2[3];
        }
    }
}

// ---------------------------------------------------------------------------
// Kernel 2: per-token projections + fused vectors copy.
// KEY CHANGE (R4->R5): stage all of Weff (64 KB) in SHARED MEMORY once per
// block. w-loads become 29-cyc conflict-free LDS instead of repeated L2 hits
// (the 128 MB v-stream was evicting g_W from L1 every k-step).
// One warp per 2 tokens; 8 warps/block -> 16 tokens/block; grid = 512.
// ---------------------------------------------------------------------------
__global__ void __launch_bounds__(256) k2_proj(const float4* __restrict__ vec4,
                                               float4* __restrict__ outv4) {
    extern __shared__ float4 sW[];  // 4096 float4 = 64 KB = all of g_W
    const float4* gW4 = reinterpret_cast<const float4*>(g_W);
    for (int s = threadIdx.x; s < 4096; s += 256) sW[s] = gW4[s];
    __syncthreads();

    const int lane = threadIdx.x & 31;
    const int wid = threadIdx.x >> 5;
    const int t0 = (blockIdx.x * 8 + wid) * 2;  // base token of this warp

    const float4* vp = vec4 + (size_t)t0 * 512;
    float4* op = outv4 + (size_t)t0 * 512;

    float acc[8][2];
#pragma unroll
    for (int r = 0; r < 8; r++) {
        acc[r][0] = 0.f;
        acc[r][1] = 0.f;
    }

#pragma unroll
    for (int k = 0; k < 16; k++) {
        const int i = lane + 32 * k;
        float4 v0 = __ldcs(&vp[i]);        // streaming: no L1 pollution
        float4 v1 = __ldcs(&vp[512 + i]);
        __stcs(&op[i], v0);                // fused streaming copy to output
        __stcs(&op[512 + i], v1);
#pragma unroll
        for (int r = 0; r < 8; r++) {
            float4 w = sW[r * 512 + i];    // LDS.128, conflict-free
            acc[r][0] = fmaf(v0.x, w.x, acc[r][0]);
            acc[r][0] = fmaf(v0.y, w.y, acc[r][0]);
            acc[r][0] = fmaf(v0.z, w.z, acc[r][0]);
            acc[r][0] = fmaf(v0.w, w.w, acc[r][0]);
            acc[r][1] = fmaf(v1.x, w.x, acc[r][1]);
            acc[r][1] = fmaf(v1.y, w.y, acc[r][1]);
            acc[r][1] = fmaf(v1.z, w.z, acc[r][1]);
            acc[r][1] = fmaf(v1.w, w.w, acc[r][1]);
        }
    }

#pragma unroll
    for (int r = 0; r < 8; r++)
#pragma unroll
        for (int t = 0; t < 2; t++)
#pragma unroll
            for (int off = 16; off; off >>= 1)
                acc[r][t] += __shfl_xor_sync(~0u, acc[r][t], off);

    if (lane == 0) {
#pragma unroll
        for (int t = 0; t < 2; t++) {
            const int token = t0 + t;
            const int b = token >> 10, n = token & 1023;
            const int base = b * 4 * 1024 + n;
#pragma unroll
            for (int c = 0; c < 4; c++) {
                g_EA[base + c * 1024] = __expf(acc[c][t] + g_cst[c]);
                g_EB[base + c * 1024] = __expf(acc[4 + c][t]);
            }
        }
    }
}

// ---------------------------------------------------------------------------
// Kernel 3: connections[b,c,m,n] = t/(1+t),  t = EA[b,c,n] * EB[b,c,m]
// grid (64, 32): blockIdx.y = (b*4+c), blockIdx.x = 16-row m tile.
// R5: preload all 16 eb up front (kills serialized load-use chains),
// streaming stores for eager DRAM drain.
// ---------------------------------------------------------------------------
__global__ void k3_conn(float4* __restrict__ conn4) {
    const int tid = threadIdx.x;       // 0..255 -> float4 group along n
    const int bc = blockIdx.y;         // 0..31
    const int m0 = blockIdx.x * 16;

    const float4* ea4 = reinterpret_cast<const float4*>(g_EA);
    const float4* eb4 = reinterpret_cast<const float4*>(g_EB);
    float4 ea = __ldg(&ea4[bc * 256 + tid]);

    // Preload the 16 eb values (broadcast loads, all independent).
    float4 e0 = __ldg(&eb4[(bc * 1024 + m0) / 4 + 0]);
    float4 e1 = __ldg(&eb4[(bc * 1024 + m0) / 4 + 1]);
    float4 e2 = __ldg(&eb4[(bc * 1024 + m0) / 4 + 2]);
    float4 e3 = __ldg(&eb4[(bc * 1024 + m0) / 4 + 3]);
    float ebv[16] = {e0.x, e0.y, e0.z, e0.w, e1.x, e1.y, e1.z, e1.w,
                     e2.x, e2.y, e2.z, e2.w, e3.x, e3.y, e3.z, e3.w};

    size_t obase = ((size_t)bc * 1024 + m0) * 256 + tid;
#pragma unroll
    for (int j = 0; j < 16; j++) {
        const float eb = ebv[j];
        float4 o;
        float t;
        t = ea.x * eb; o.x = __fdividef(t, 1.0f + t);
        t = ea.y * eb; o.y = __fdividef(t, 1.0f + t);
        t = ea.z * eb; o.z = __fdividef(t, 1.0f + t);
        t = ea.w * eb; o.w = __fdividef(t, 1.0f + t);
        __stcs(&conn4[obase + (size_t)j * 256], o);
    }
}

// ---------------------------------------------------------------------------
extern "C" void kernel_launch(void* const* d_in, const int* in_sizes, int n_in,
                              void* d_out, int out_size) {
    const float* vectors = (const float*)d_in[0];
    const float* W1 = (const float*)d_in[1];
    const float* b1 = (const float*)d_in[2];
    const float* W2 = (const float*)d_in[3];
    const float* b2 = (const float*)d_in[4];
    float* out = (float*)d_out;

    // 64 KB dynamic smem for k2's weight stage (above the 48 KB default).
    cudaFuncSetAttribute(k2_proj, cudaFuncAttributeMaxDynamicSharedMemorySize,
                         64 * 1024);

    k1_weff_part<<<dim3(16, 16), 256>>>(W1, W2);
    k1b_reduce<<<64, 256>>>(W2, b1, b2);
    k2_proj<<<512, 256, 64 * 1024>>>((const float4*)vectors, (float4*)out);
    k3_conn<<<dim3(64, 32), 256>>>((float4*)(out + VEC_ELEMS));
}